// round 1
// baseline (speedup 1.0000x reference)
#include <cuda_runtime.h>

namespace {
constexpr int N_ROWS = 2048;   // x rows
constexpr int DIM    = 256;    // feature dim
constexpr int T_TRK  = 256;    // tracks
constexpr int NY     = 16384;  // T*Q flattened y rows
constexpr int NCOL   = NY + N_ROWS;  // 18432 total "columns" (yf then x)
constexpr int BM = 128, BN = 128, BK = 16;
constexpr int NCT   = NCOL / BN;   // 144 column tiles
constexpr int NCT_Y = NY / BN;     // 128 tiles belong to yf
constexpr int NRT   = N_ROWS / BM; // 16 row tiles
constexpr float INV_TEMP = 1.0f / 0.3f;
}

// Deterministic scratch (no atomics, no runtime allocation).
__device__ float g_partial[N_ROWS * NCT * 2];  // [row][ct][{total, pos}]
__device__ float g_rowbuf[N_ROWS * 2];         // [row][{num, den}]

// ---------------------------------------------------------------------------
// Fused exp-GEMM: computes exp(x @ C^T / TEMP) tile, reduces each row within
// the tile into (total, group-matched) sums; C = concat(yf, x).
// ---------------------------------------------------------------------------
__global__ void __launch_bounds__(256, 2)
gemm_fused(const float* __restrict__ x,
           const float* __restrict__ y,
           const int*   __restrict__ trk) {
    const int ct = blockIdx.x;   // 0..143
    const int rt = blockIdx.y;   // 0..15
    const int tid = threadIdx.x; // 0..255
    const int tx = tid & 15;
    const int ty = tid >> 4;

    __shared__ float As[BK][BM];
    __shared__ float Bs[BK][BN];

    const bool isxx = (ct >= NCT_Y);
    const float* Ab = x + rt * BM * DIM;
    const float* Bb = isxx ? (x + (ct - NCT_Y) * BN * DIM)
                           : (y + ct * BN * DIM);

    float acc[8][8];
#pragma unroll
    for (int i = 0; i < 8; ++i)
#pragma unroll
        for (int j = 0; j < 8; ++j) acc[i][j] = 0.0f;

    for (int kt = 0; kt < DIM / BK; ++kt) {
        // Load 128x16 A and B tiles (512 float4 each; 2 per thread), store
        // K-major (transposed) into SMEM.
#pragma unroll
        for (int c = 0; c < 2; ++c) {
            int idx = tid + c * 256;     // 0..511
            int r   = idx >> 2;          // 0..127 (tile row)
            int q   = (idx & 3) << 2;    // 0,4,8,12 (k offset)
            float4 av = *(const float4*)(Ab + r * DIM + kt * BK + q);
            float4 bv = *(const float4*)(Bb + r * DIM + kt * BK + q);
            As[q + 0][r] = av.x; As[q + 1][r] = av.y;
            As[q + 2][r] = av.z; As[q + 3][r] = av.w;
            Bs[q + 0][r] = bv.x; Bs[q + 1][r] = bv.y;
            Bs[q + 2][r] = bv.z; Bs[q + 3][r] = bv.w;
        }
        __syncthreads();

#pragma unroll
        for (int k = 0; k < BK; ++k) {
            float a[8], b[8];
            *(float4*)&a[0] = *(const float4*)&As[k][ty * 8];
            *(float4*)&a[4] = *(const float4*)&As[k][ty * 8 + 4];
            *(float4*)&b[0] = *(const float4*)&Bs[k][tx * 8];
            *(float4*)&b[4] = *(const float4*)&Bs[k][tx * 8 + 4];
#pragma unroll
            for (int i = 0; i < 8; ++i)
#pragma unroll
                for (int j = 0; j < 8; ++j)
                    acc[i][j] = fmaf(a[i], b[j], acc[i][j]);
        }
        __syncthreads();
    }

    // --- epilogue: exp + per-row reduction -------------------------------
    int gi[8];
#pragma unroll
    for (int i = 0; i < 8; ++i) gi[i] = trk[rt * BM + ty * 8 + i];

    int gj[8];
    if (!isxx) {
        // y column j's group id is (global j) % 256; ct*128 % 256 = (ct&1)*128
        const int base = (ct & 1) * 128 + tx * 8;
#pragma unroll
        for (int j = 0; j < 8; ++j) gj[j] = base + j;
    } else {
        const int base = (ct - NCT_Y) * BN + tx * 8;
#pragma unroll
        for (int j = 0; j < 8; ++j) gj[j] = trk[base + j];
    }

    float tot[8], pos[8];
#pragma unroll
    for (int i = 0; i < 8; ++i) { tot[i] = 0.0f; pos[i] = 0.0f; }

#pragma unroll
    for (int i = 0; i < 8; ++i) {
#pragma unroll
        for (int j = 0; j < 8; ++j) {
            float e = __expf(acc[i][j] * INV_TEMP);
            tot[i] += e;
            if (gj[j] == gi[i]) pos[i] += e;
        }
    }

    // Butterfly reduce across the 16 tx lanes (stays inside 16-lane groups).
#pragma unroll
    for (int off = 8; off >= 1; off >>= 1) {
#pragma unroll
        for (int i = 0; i < 8; ++i) {
            tot[i] += __shfl_xor_sync(0xffffffffu, tot[i], off);
            pos[i] += __shfl_xor_sync(0xffffffffu, pos[i], off);
        }
    }

    if (tx == 0) {
#pragma unroll
        for (int i = 0; i < 8; ++i) {
            int row = rt * BM + ty * 8 + i;
            float* p = g_partial + (row * NCT + ct) * 2;
            p[0] = tot[i];
            p[1] = pos[i];
        }
    }
}

// ---------------------------------------------------------------------------
// Per-row reduction over column tiles + diagonal exclusion.
// ---------------------------------------------------------------------------
__global__ void reduce_rows(const float* __restrict__ x) {
    int row = blockIdx.x * blockDim.x + threadIdx.x;
    if (row >= N_ROWS) return;

    float tot = 0.0f, posxy = 0.0f, posxx = 0.0f;
    const float* p = g_partial + row * NCT * 2;
#pragma unroll 4
    for (int ct = 0; ct < NCT; ++ct) {
        tot += p[2 * ct];
        if (ct < NCT_Y) posxy += p[2 * ct + 1];
        else            posxx += p[2 * ct + 1];
    }

    // diag = exp(|x_row|^2 / TEMP)
    float sd = 0.0f;
    const float4* xr = (const float4*)(x + row * DIM);
#pragma unroll 8
    for (int k = 0; k < DIM / 4; ++k) {
        float4 v = xr[k];
        sd += v.x * v.x + v.y * v.y + v.z * v.z + v.w * v.w;
    }
    float diag = __expf(sd * INV_TEMP);

    // num_i = rxy_pos + 0.5*(rxx_pos_full - diag)
    // den_i = (rxy_total + rxx_total) - rxy_pos - rxx_pos_full
    g_rowbuf[row * 2 + 0] = posxy + 0.5f * (posxx - diag);
    g_rowbuf[row * 2 + 1] = tot - posxy - posxx;
}

// ---------------------------------------------------------------------------
// Deterministic segment sum over tracks + final loss.
// ---------------------------------------------------------------------------
__global__ void finalize(const int* __restrict__ trk, float* __restrict__ out) {
    const int t = threadIdx.x;  // track id, 0..255
    float num = 0.0f, den = 0.0f;
    int cnt = 0;
    for (int r = 0; r < N_ROWS; ++r) {
        if (trk[r] == t) {
            num += g_rowbuf[2 * r];
            den += g_rowbuf[2 * r + 1];
            ++cnt;
        }
    }
    float loss = 0.0f;
    int present = (cnt > 0) ? 1 : 0;
    if (present) loss = -logf(num / (den + num));

    __shared__ float sl[256];
    __shared__ int   sp[256];
    sl[t] = loss;
    sp[t] = present;
    __syncthreads();
    for (int s = 128; s > 0; s >>= 1) {
        if (t < s) { sl[t] += sl[t + s]; sp[t] += sp[t + s]; }
        __syncthreads();
    }
    if (t == 0) out[0] = sl[0] / (float)sp[0];
}

// ---------------------------------------------------------------------------
extern "C" void kernel_launch(void* const* d_in, const int* in_sizes, int n_in,
                              void* d_out, int out_size) {
    const float* x   = (const float*)d_in[0];
    const int*   trk = (const int*)  d_in[1];
    const float* y   = (const float*)d_in[2];

    dim3 grid(NCT, NRT);
    gemm_fused<<<grid, 256>>>(x, y, trk);
    reduce_rows<<<N_ROWS / 256, 256>>>(x);
    finalize<<<1, 256>>>(trk, (float*)d_out);
}

// round 3
// speedup vs baseline: 3.0030x; 3.0030x over previous
#include <cuda_runtime.h>
#include <cstdint>

namespace {
constexpr int N_ROWS = 2048;
constexpr int DIM    = 256;
constexpr int NY     = 16384;          // T*Q
constexpr int NCOL   = NY + N_ROWS;    // 18432
constexpr int BM = 128, BN = 128;
constexpr int NCT   = NCOL / BN;       // 144 column tiles
constexpr int NCT_Y = NY / BN;         // 128 are y-tiles
constexpr int NRT   = N_ROWS / BM;     // 16 row tiles
constexpr int KC     = 16;             // K per smem stage
constexpr int NSTAGE = DIM / KC;       // 16
constexpr int RS     = 20;             // smem row stride (floats): 16 + 4 pad
constexpr int TB     = BM * RS * 4;    // 10240 B per tile buffer

constexpr uint32_t OFF_B   = 2 * TB;          // B buffers after 2 A buffers
constexpr uint32_t OFF_GJ  = 4 * TB;          // 40960: 128 col group ids
constexpr uint32_t OFF_GI  = OFF_GJ + 512;    // 128 row group ids
constexpr uint32_t OFF_CMB = OFF_GI + 512;    // 128 float2 combine buffer
constexpr uint32_t SMEM_BYTES = OFF_CMB + 1024;  // 43008 < 48K default

constexpr float EXP_SCALE = 1.44269504088896340736f / 0.3f;  // log2(e)/TEMP
constexpr float INV_TEMP  = 1.0f / 0.3f;
}

__device__ float g_partial[N_ROWS * NCT * 2];  // [row][ct][{tot,pos}]
__device__ float g_rowbuf[N_ROWS * 2];         // [row][{num,den}]

__device__ __forceinline__ uint32_t smem_u32(const void* p) {
    uint32_t a;
    asm("{ .reg .u64 t; cvta.to.shared.u64 t, %1; cvt.u32.u64 %0, t; }" : "=r"(a) : "l"(p));
    return a;
}
__device__ __forceinline__ void cp16(uint32_t saddr, const void* g) {
    asm volatile("cp.async.cg.shared.global [%0], [%1], 16;" :: "r"(saddr), "l"(g));
}
__device__ __forceinline__ float fexp2(float z) {
    float r;
    asm("ex2.approx.f32 %0, %1;" : "=f"(r) : "f"(z));
    return r;
}
__device__ __forceinline__ void mma_tf32(float* d, const uint32_t* a,
                                         uint32_t b0, uint32_t b1) {
    asm volatile(
        "mma.sync.aligned.m16n8k8.row.col.f32.tf32.tf32.f32 "
        "{%0,%1,%2,%3},{%4,%5,%6,%7},{%8,%9},{%0,%1,%2,%3};"
        : "+f"(d[0]), "+f"(d[1]), "+f"(d[2]), "+f"(d[3])
        : "r"(a[0]), "r"(a[1]), "r"(a[2]), "r"(a[3]), "r"(b0), "r"(b1));
}

// ---------------------------------------------------------------------------
// tf32 mma.sync fused exp-GEMM with per-row (total, group-matched) reduction.
// ---------------------------------------------------------------------------
__global__ void __launch_bounds__(256, 2)
gemm_tc(const float* __restrict__ x, const float* __restrict__ y,
        const int* __restrict__ trk) {
    extern __shared__ char smem[];
    const uint32_t sbase = smem_u32(smem);
    const int tid  = threadIdx.x;
    const int wid  = tid >> 5, lid = tid & 31;
    const int wm   = wid & 3, wn = wid >> 2;      // 4 x 2 warp grid
    const int quad = lid >> 2, qi = lid & 3;
    const int ct = blockIdx.x;   // 0..143
    const int rt = blockIdx.y;   // 0..15

    int* sGJ = (int*)(smem + OFF_GJ);
    int* sGI = (int*)(smem + OFF_GI);
    if (tid < BM) {
        sGI[tid] = trk[rt * BM + tid];
        // y col group = global col % 256; tile base % 256 = (ct&1)*128
        sGJ[tid] = (ct < NCT_Y) ? ((ct & 1) * 128 + tid)
                                : trk[(ct - NCT_Y) * BN + tid];
    }

    const float* Ab = x + (size_t)rt * BM * DIM;
    const float* Bb = (ct < NCT_Y) ? (y + (size_t)ct * BN * DIM)
                                   : (x + (size_t)(ct - NCT_Y) * BN * DIM);

    float acc[2][8][4];
#pragma unroll
    for (int fi = 0; fi < 2; ++fi)
#pragma unroll
        for (int nf = 0; nf < 8; ++nf)
#pragma unroll
            for (int r = 0; r < 4; ++r) acc[fi][nf][r] = 0.0f;

    // ---- stage issue: 512 A chunks + 512 B chunks of 16B (2+2 per thread)
    auto issue_stage = [&](int s, int buf) {
#pragma unroll
        for (int i = 0; i < 2; ++i) {
            int id = tid + 256 * i;
            int r = id >> 2, q = id & 3;
            cp16(sbase + buf * TB + r * (RS * 4) + q * 16,
                 Ab + (size_t)r * DIM + s * KC + q * 4);
        }
#pragma unroll
        for (int i = 0; i < 2; ++i) {
            int id = tid + 256 * i;
            int r = id >> 2, q = id & 3;
            cp16(sbase + OFF_B + buf * TB + r * (RS * 4) + q * 16,
                 Bb + (size_t)r * DIM + s * KC + q * 4);
        }
        asm volatile("cp.async.commit_group;" ::: "memory");
    };

    issue_stage(0, 0);

    for (int s = 0; s < NSTAGE; ++s) {
        const int buf = s & 1;
        if (s + 1 < NSTAGE) {
            issue_stage(s + 1, (s + 1) & 1);
            asm volatile("cp.async.wait_group 1;" ::: "memory");
        } else {
            asm volatile("cp.async.wait_group 0;" ::: "memory");
        }
        __syncthreads();

        const float* As = (const float*)(smem + buf * TB);
        const float* Bs = (const float*)(smem + OFF_B + buf * TB);
        const float* ap = As + (wm * 32 + quad) * RS + qi;
        const float* bp = Bs + (wn * 64 + quad) * RS + qi;
#pragma unroll
        for (int k = 0; k < KC / 8; ++k) {       // 2 k-steps of 8
            uint32_t a[2][4];
#pragma unroll
            for (int fi = 0; fi < 2; ++fi) {
                const float* p = ap + fi * 16 * RS + k * 8;
                a[fi][0] = __float_as_uint(p[0]);
                a[fi][1] = __float_as_uint(p[8 * RS]);
                a[fi][2] = __float_as_uint(p[4]);
                a[fi][3] = __float_as_uint(p[8 * RS + 4]);
            }
#pragma unroll
            for (int nf = 0; nf < 8; ++nf) {
                const float* p = bp + nf * 8 * RS + k * 8;
                uint32_t b0 = __float_as_uint(p[0]);
                uint32_t b1 = __float_as_uint(p[4]);
                mma_tf32(acc[0][nf], a[0], b0, b1);
                mma_tf32(acc[1][nf], a[1], b0, b1);
            }
        }
        __syncthreads();   // protect buf reuse at next issue
    }

    // ---- epilogue: exp + group-matched row sums, straight from fragments.
    // Fragment (fi,nf): rows r0 = wm*32+fi*16+quad, r1 = r0+8;
    //                   cols c0 = wn*64+nf*8+2*qi, c1 = c0+1.
    float2* CMB = (float2*)(smem + OFF_CMB);
#pragma unroll
    for (int fi = 0; fi < 2; ++fi) {
        const int r0 = wm * 32 + fi * 16 + quad;
        const int r1 = r0 + 8;
        const int gi0 = sGI[r0], gi1 = sGI[r1];
        float t0 = 0.f, p0 = 0.f, t1 = 0.f, p1 = 0.f;
#pragma unroll
        for (int nf = 0; nf < 8; ++nf) {
            const int c0 = wn * 64 + nf * 8 + 2 * qi;
            const int gj0 = sGJ[c0], gj1 = sGJ[c0 + 1];
            float e;
            e = fexp2(acc[fi][nf][0] * EXP_SCALE); t0 += e; if (gj0 == gi0) p0 += e;
            e = fexp2(acc[fi][nf][1] * EXP_SCALE); t0 += e; if (gj1 == gi0) p0 += e;
            e = fexp2(acc[fi][nf][2] * EXP_SCALE); t1 += e; if (gj0 == gi1) p1 += e;
            e = fexp2(acc[fi][nf][3] * EXP_SCALE); t1 += e; if (gj1 == gi1) p1 += e;
        }
        // reduce across the 4 lanes of the quad (same rows, different cols)
#pragma unroll
        for (int o = 1; o <= 2; o <<= 1) {
            t0 += __shfl_xor_sync(0xffffffffu, t0, o);
            p0 += __shfl_xor_sync(0xffffffffu, p0, o);
            t1 += __shfl_xor_sync(0xffffffffu, t1, o);
            p1 += __shfl_xor_sync(0xffffffffu, p1, o);
        }
        if (qi == 0 && wn == 1) {
            CMB[r0] = make_float2(t0, p0);
            CMB[r1] = make_float2(t1, p1);
        }
        // stash for wn==0 path after sync
        if (fi == 0) { acc[0][0][0] = t0; acc[0][0][1] = p0; acc[0][0][2] = t1; acc[0][0][3] = p1; }
        else         { acc[1][0][0] = t0; acc[1][0][1] = p0; acc[1][0][2] = t1; acc[1][0][3] = p1; }
    }
    __syncthreads();
    if (qi == 0 && wn == 0) {
#pragma unroll
        for (int fi = 0; fi < 2; ++fi) {
            const int r0 = wm * 32 + fi * 16 + quad;
            const int r1 = r0 + 8;
            float2 o0 = CMB[r0], o1 = CMB[r1];
            float* g0 = g_partial + (((size_t)(rt * BM + r0)) * NCT + ct) * 2;
            float* g1 = g_partial + (((size_t)(rt * BM + r1)) * NCT + ct) * 2;
            g0[0] = acc[fi][0][0] + o0.x;
            g0[1] = acc[fi][0][1] + o0.y;
            g1[0] = acc[fi][0][2] + o1.x;
            g1[1] = acc[fi][0][3] + o1.y;
        }
    }
}

// ---------------------------------------------------------------------------
// Warp-per-row reduction over column tiles + diagonal exclusion.
// ---------------------------------------------------------------------------
__global__ void __launch_bounds__(256)
reduce_rows(const float* __restrict__ x) {
    const int row = blockIdx.x * 8 + (threadIdx.x >> 5);
    const int l = threadIdx.x & 31;

    float tot = 0.f, pxy = 0.f, pxx = 0.f;
    const float* p = g_partial + (size_t)row * NCT * 2;
    for (int ctv = l; ctv < NCT; ctv += 32) {
        tot += p[2 * ctv];
        float q = p[2 * ctv + 1];
        if (ctv < NCT_Y) pxy += q; else pxx += q;
    }
    const float4* xr = (const float4*)(x + (size_t)row * DIM);
    float sd = 0.f;
    for (int k = l; k < DIM / 4; k += 32) {
        float4 v = xr[k];
        sd += v.x * v.x + v.y * v.y + v.z * v.z + v.w * v.w;
    }
#pragma unroll
    for (int o = 16; o; o >>= 1) {
        tot += __shfl_xor_sync(0xffffffffu, tot, o);
        pxy += __shfl_xor_sync(0xffffffffu, pxy, o);
        pxx += __shfl_xor_sync(0xffffffffu, pxx, o);
        sd  += __shfl_xor_sync(0xffffffffu, sd,  o);
    }
    if (l == 0) {
        float diag = __expf(sd * INV_TEMP);
        g_rowbuf[row * 2 + 0] = pxy + 0.5f * (pxx - diag);
        g_rowbuf[row * 2 + 1] = tot - pxy - pxx;
    }
}

// ---------------------------------------------------------------------------
// Deterministic segment sum over tracks + final loss (smem-staged scan).
// ---------------------------------------------------------------------------
__global__ void __launch_bounds__(256)
finalize(const int* __restrict__ trk, float* __restrict__ out) {
    __shared__ float snum[N_ROWS], sden[N_ROWS];
    __shared__ int   strk[N_ROWS];
    const int t = threadIdx.x;  // track id, 0..255
    for (int r = t; r < N_ROWS; r += 256) {
        snum[r] = g_rowbuf[2 * r];
        sden[r] = g_rowbuf[2 * r + 1];
        strk[r] = trk[r];
    }
    __syncthreads();

    float num = 0.f, den = 0.f;
    int cnt = 0;
#pragma unroll 4
    for (int r = 0; r < N_ROWS; ++r) {
        if (strk[r] == t) { num += snum[r]; den += sden[r]; ++cnt; }
    }
    float loss = 0.f;
    int present = (cnt > 0) ? 1 : 0;
    if (present) loss = -logf(num / (den + num));

    __shared__ float sl[256];
    __shared__ int   sp[256];
    sl[t] = loss;
    sp[t] = present;
    __syncthreads();
    for (int s = 128; s > 0; s >>= 1) {
        if (t < s) { sl[t] += sl[t + s]; sp[t] += sp[t + s]; }
        __syncthreads();
    }
    if (t == 0) out[0] = sl[0] / (float)sp[0];
}

// ---------------------------------------------------------------------------
extern "C" void kernel_launch(void* const* d_in, const int* in_sizes, int n_in,
                              void* d_out, int out_size) {
    const float* x   = (const float*)d_in[0];
    const int*   trk = (const int*)  d_in[1];
    const float* y   = (const float*)d_in[2];

    dim3 grid(NCT, NRT);
    gemm_tc<<<grid, 256, SMEM_BYTES>>>(x, y, trk);
    reduce_rows<<<N_ROWS / 8, 256>>>(x);
    finalize<<<1, 256>>>(trk, (float*)d_out);
}

// round 4
// speedup vs baseline: 3.5410x; 1.1791x over previous
#include <cuda_runtime.h>
#include <cstdint>

namespace {
constexpr int N_ROWS = 2048;
constexpr int DIM    = 256;
constexpr int NY     = 16384;          // T*Q
constexpr int NCOL   = NY + N_ROWS;    // 18432
constexpr int BM = 128, BN = 128;
constexpr int NCT   = NCOL / BN;       // 144 column tiles
constexpr int NCT_Y = NY / BN;         // 128 are y-tiles
constexpr int NRT   = N_ROWS / BM;     // 16 row tiles
constexpr int KC     = 32;             // K per smem stage
constexpr int NSTAGE = DIM / KC;       // 8
constexpr int RS     = 36;             // smem row stride (floats): 32 + 4 pad (144B = 9*16)
constexpr int TB     = BM * RS * 4;    // 18432 B per tile buffer

constexpr uint32_t OFF_B   = 2 * TB;          // B buffers after 2 A buffers
constexpr uint32_t OFF_GJ  = 4 * TB;          // 73728: 128 col group ids
constexpr uint32_t OFF_GI  = OFF_GJ + 512;
constexpr uint32_t OFF_CMB = OFF_GI + 512;    // 128 float2 combine buffer
constexpr uint32_t SMEM_BYTES = OFF_CMB + 1024;  // 75776

constexpr float EXP_SCALE = 1.44269504088896340736f / 0.3f;  // log2(e)/TEMP
constexpr float INV_TEMP  = 1.0f / 0.3f;
}

__device__ float g_partial[N_ROWS * NCT * 2];  // [row][ct][{tot,pos}]
__device__ float g_rowbuf[N_ROWS * 2];         // [row][{num,den}]

__device__ __forceinline__ uint32_t smem_u32(const void* p) {
    uint32_t a;
    asm("{ .reg .u64 t; cvta.to.shared.u64 t, %1; cvt.u32.u64 %0, t; }" : "=r"(a) : "l"(p));
    return a;
}
__device__ __forceinline__ void cp16(uint32_t saddr, const void* g) {
    asm volatile("cp.async.cg.shared.global [%0], [%1], 16;" :: "r"(saddr), "l"(g));
}
__device__ __forceinline__ float fexp2(float z) {
    float r;
    asm("ex2.approx.f32 %0, %1;" : "=f"(r) : "f"(z));
    return r;
}
__device__ __forceinline__ void mma_tf32(float* d, const uint32_t* a,
                                         uint32_t b0, uint32_t b1) {
    asm volatile(
        "mma.sync.aligned.m16n8k8.row.col.f32.tf32.tf32.f32 "
        "{%0,%1,%2,%3},{%4,%5,%6,%7},{%8,%9},{%0,%1,%2,%3};"
        : "+f"(d[0]), "+f"(d[1]), "+f"(d[2]), "+f"(d[3])
        : "r"(a[0]), "r"(a[1]), "r"(a[2]), "r"(a[3]), "r"(b0), "r"(b1));
}

// ---------------------------------------------------------------------------
// tf32 mma.sync fused exp-GEMM with per-row (total, group-matched) reduction.
// ---------------------------------------------------------------------------
__global__ void __launch_bounds__(256, 2)
gemm_tc(const float* __restrict__ x, const float* __restrict__ y,
        const int* __restrict__ trk) {
    extern __shared__ char smem[];
    const uint32_t sbase = smem_u32(smem);
    const int tid  = threadIdx.x;
    const int wid  = tid >> 5, lid = tid & 31;
    const int wm   = wid & 3, wn = wid >> 2;      // 4 x 2 warp grid
    const int quad = lid >> 2, qi = lid & 3;
    const int ct = blockIdx.x;   // 0..143
    const int rt = blockIdx.y;   // 0..15

    int* sGJ = (int*)(smem + OFF_GJ);
    int* sGI = (int*)(smem + OFF_GI);
    if (tid < BM) {
        sGI[tid] = trk[rt * BM + tid];
        // y col group = global col % 256; tile base % 256 = (ct&1)*128
        sGJ[tid] = (ct < NCT_Y) ? ((ct & 1) * 128 + tid)
                                : trk[(ct - NCT_Y) * BN + tid];
    }

    const float* Ab = x + (size_t)rt * BM * DIM;
    const float* Bb = (ct < NCT_Y) ? (y + (size_t)ct * BN * DIM)
                                   : (x + (size_t)(ct - NCT_Y) * BN * DIM);

    float acc[2][8][4];
#pragma unroll
    for (int fi = 0; fi < 2; ++fi)
#pragma unroll
        for (int nf = 0; nf < 8; ++nf)
#pragma unroll
            for (int r = 0; r < 4; ++r) acc[fi][nf][r] = 0.0f;

    // ---- stage issue: 1024 A chunks + 1024 B chunks of 16B (4+4 per thread)
    auto issue_stage = [&](int s, int buf) {
#pragma unroll
        for (int i = 0; i < 4; ++i) {
            int id = tid + 256 * i;
            int r = id >> 3, q = id & 7;
            cp16(sbase + buf * TB + r * (RS * 4) + q * 16,
                 Ab + (size_t)r * DIM + s * KC + q * 4);
        }
#pragma unroll
        for (int i = 0; i < 4; ++i) {
            int id = tid + 256 * i;
            int r = id >> 3, q = id & 7;
            cp16(sbase + OFF_B + buf * TB + r * (RS * 4) + q * 16,
                 Bb + (size_t)r * DIM + s * KC + q * 4);
        }
        asm volatile("cp.async.commit_group;" ::: "memory");
    };

    issue_stage(0, 0);

    for (int s = 0; s < NSTAGE; ++s) {
        const int buf = s & 1;
        if (s + 1 < NSTAGE) {
            issue_stage(s + 1, (s + 1) & 1);
            asm volatile("cp.async.wait_group 1;" ::: "memory");
        } else {
            asm volatile("cp.async.wait_group 0;" ::: "memory");
        }
        __syncthreads();

        const float* As = (const float*)(smem + buf * TB);
        const float* Bs = (const float*)(smem + OFF_B + buf * TB);
        const float* ap = As + (wm * 32 + quad) * RS + qi;
        const float* bp = Bs + (wn * 64 + quad) * RS + qi;
#pragma unroll
        for (int k = 0; k < KC / 8; ++k) {       // 4 k-steps of 8
            uint32_t a[2][4];
#pragma unroll
            for (int fi = 0; fi < 2; ++fi) {
                const float* p = ap + fi * 16 * RS + k * 8;
                a[fi][0] = __float_as_uint(p[0]);
                a[fi][1] = __float_as_uint(p[8 * RS]);
                a[fi][2] = __float_as_uint(p[4]);
                a[fi][3] = __float_as_uint(p[8 * RS + 4]);
            }
#pragma unroll
            for (int nf = 0; nf < 8; ++nf) {
                const float* p = bp + nf * 8 * RS + k * 8;
                uint32_t b0 = __float_as_uint(p[0]);
                uint32_t b1 = __float_as_uint(p[4]);
                mma_tf32(acc[0][nf], a[0], b0, b1);
                mma_tf32(acc[1][nf], a[1], b0, b1);
            }
        }
        __syncthreads();   // protect buf reuse at next issue
    }

    // ---- epilogue: exp + group-matched row sums, straight from fragments.
    float2* CMB = (float2*)(smem + OFF_CMB);
#pragma unroll
    for (int fi = 0; fi < 2; ++fi) {
        const int r0 = wm * 32 + fi * 16 + quad;
        const int r1 = r0 + 8;
        const int gi0 = sGI[r0], gi1 = sGI[r1];
        float t0 = 0.f, p0 = 0.f, t1 = 0.f, p1 = 0.f;
#pragma unroll
        for (int nf = 0; nf < 8; ++nf) {
            const int c0 = wn * 64 + nf * 8 + 2 * qi;
            const int gj0 = sGJ[c0], gj1 = sGJ[c0 + 1];
            float e;
            e = fexp2(acc[fi][nf][0] * EXP_SCALE); t0 += e; if (gj0 == gi0) p0 += e;
            e = fexp2(acc[fi][nf][1] * EXP_SCALE); t0 += e; if (gj1 == gi0) p0 += e;
            e = fexp2(acc[fi][nf][2] * EXP_SCALE); t1 += e; if (gj0 == gi1) p1 += e;
            e = fexp2(acc[fi][nf][3] * EXP_SCALE); t1 += e; if (gj1 == gi1) p1 += e;
        }
#pragma unroll
        for (int o = 1; o <= 2; o <<= 1) {
            t0 += __shfl_xor_sync(0xffffffffu, t0, o);
            p0 += __shfl_xor_sync(0xffffffffu, p0, o);
            t1 += __shfl_xor_sync(0xffffffffu, t1, o);
            p1 += __shfl_xor_sync(0xffffffffu, p1, o);
        }
        if (qi == 0 && wn == 1) {
            CMB[r0] = make_float2(t0, p0);
            CMB[r1] = make_float2(t1, p1);
        }
        if (fi == 0) { acc[0][0][0] = t0; acc[0][0][1] = p0; acc[0][0][2] = t1; acc[0][0][3] = p1; }
        else         { acc[1][0][0] = t0; acc[1][0][1] = p0; acc[1][0][2] = t1; acc[1][0][3] = p1; }
    }
    __syncthreads();
    if (qi == 0 && wn == 0) {
#pragma unroll
        for (int fi = 0; fi < 2; ++fi) {
            const int r0 = wm * 32 + fi * 16 + quad;
            const int r1 = r0 + 8;
            float2 o0 = CMB[r0], o1 = CMB[r1];
            float* g0 = g_partial + (((size_t)(rt * BM + r0)) * NCT + ct) * 2;
            float* g1 = g_partial + (((size_t)(rt * BM + r1)) * NCT + ct) * 2;
            g0[0] = acc[fi][0][0] + o0.x;
            g0[1] = acc[fi][0][1] + o0.y;
            g1[0] = acc[fi][0][2] + o1.x;
            g1[1] = acc[fi][0][3] + o1.y;
        }
    }
}

// ---------------------------------------------------------------------------
// Warp-per-row reduction over column tiles + diagonal exclusion.
// ---------------------------------------------------------------------------
__global__ void __launch_bounds__(256)
reduce_rows(const float* __restrict__ x) {
    const int row = blockIdx.x * 8 + (threadIdx.x >> 5);
    const int l = threadIdx.x & 31;

    float tot = 0.f, pxy = 0.f, pxx = 0.f;
    const float* p = g_partial + (size_t)row * NCT * 2;
    for (int ctv = l; ctv < NCT; ctv += 32) {
        tot += p[2 * ctv];
        float q = p[2 * ctv + 1];
        if (ctv < NCT_Y) pxy += q; else pxx += q;
    }
    const float4* xr = (const float4*)(x + (size_t)row * DIM);
    float sd = 0.f;
    for (int k = l; k < DIM / 4; k += 32) {
        float4 v = xr[k];
        sd += v.x * v.x + v.y * v.y + v.z * v.z + v.w * v.w;
    }
#pragma unroll
    for (int o = 16; o; o >>= 1) {
        tot += __shfl_xor_sync(0xffffffffu, tot, o);
        pxy += __shfl_xor_sync(0xffffffffu, pxy, o);
        pxx += __shfl_xor_sync(0xffffffffu, pxx, o);
        sd  += __shfl_xor_sync(0xffffffffu, sd,  o);
    }
    if (l == 0) {
        float diag = __expf(sd * INV_TEMP);
        g_rowbuf[row * 2 + 0] = pxy + 0.5f * (pxx - diag);
        g_rowbuf[row * 2 + 1] = tot - pxy - pxx;
    }
}

// ---------------------------------------------------------------------------
// Deterministic segment sum over tracks + final loss (smem-staged scan).
// ---------------------------------------------------------------------------
__global__ void __launch_bounds__(256)
finalize(const int* __restrict__ trk, float* __restrict__ out) {
    __shared__ float snum[N_ROWS], sden[N_ROWS];
    __shared__ int   strk[N_ROWS];
    const int t = threadIdx.x;  // track id, 0..255
    for (int r = t; r < N_ROWS; r += 256) {
        snum[r] = g_rowbuf[2 * r];
        sden[r] = g_rowbuf[2 * r + 1];
        strk[r] = trk[r];
    }
    __syncthreads();

    float num = 0.f, den = 0.f;
    int cnt = 0;
#pragma unroll 4
    for (int r = 0; r < N_ROWS; ++r) {
        if (strk[r] == t) { num += snum[r]; den += sden[r]; ++cnt; }
    }
    float loss = 0.f;
    int present = (cnt > 0) ? 1 : 0;
    if (present) loss = -logf(num / (den + num));

    __shared__ float sl[256];
    __shared__ int   sp[256];
    sl[t] = loss;
    sp[t] = present;
    __syncthreads();
    for (int s = 128; s > 0; s >>= 1) {
        if (t < s) { sl[t] += sl[t + s]; sp[t] += sp[t + s]; }
        __syncthreads();
    }
    if (t == 0) out[0] = sl[0] / (float)sp[0];
}

// ---------------------------------------------------------------------------
extern "C" void kernel_launch(void* const* d_in, const int* in_sizes, int n_in,
                              void* d_out, int out_size) {
    const float* x   = (const float*)d_in[0];
    const int*   trk = (const int*)  d_in[1];
    const float* y   = (const float*)d_in[2];

    cudaFuncSetAttribute(gemm_tc, cudaFuncAttributeMaxDynamicSharedMemorySize,
                         (int)SMEM_BYTES);

    dim3 grid(NCT, NRT);
    gemm_tc<<<grid, 256, SMEM_BYTES>>>(x, y, trk);
    reduce_rows<<<N_ROWS / 8, 256>>>(x);
    finalize<<<1, 256>>>(trk, (float*)d_out);
}